// round 4
// baseline (speedup 1.0000x reference)
#include <cuda_runtime.h>
#include <cuda_bf16.h>
#include <cstdint>

// Problem constants
constexpr int B_  = 64;
constexpr int N_  = 5000;
constexpr int C_  = 64;
constexpr int NCOL = B_ * C_;          // 4096
constexpr int XROW = N_ * C_;          // 320000

// GEMM tiling
constexpr int TM = 128;
constexpr int TN = 256;
constexpr int TK = 32;
constexpr int KC = (N_ + TK - 1) / TK;  // 157

// Scratch (device globals; no allocation)
__device__ __align__(1024) __nv_bfloat16 g_Sh[(size_t)N_ * N_];    // 50 MB
__device__ __align__(1024) __nv_bfloat16 g_Sl[(size_t)N_ * N_];    // 50 MB
__device__ __align__(1024) __nv_bfloat16 g_Bh[(size_t)NCOL * N_];  // 41 MB
__device__ __align__(1024) __nv_bfloat16 g_Bl[(size_t)NCOL * N_];  // 41 MB
__device__ __align__(1024) float         g_G [(size_t)N_ * NCOL];  // 82 MB
__device__ __align__(1024) float         g_W [(size_t)N_ * 8192];  // 164 MB

// ---------------------------------------------------------------------------
// Helpers
// ---------------------------------------------------------------------------
__device__ __forceinline__ uint32_t smem_u32(const void* p) {
    uint32_t a;
    asm("{ .reg .u64 t; cvta.to.shared.u64 t, %1; cvt.u32.u64 %0, t; }" : "=r"(a) : "l"(p));
    return a;
}
__device__ __forceinline__ uint32_t swz(uint32_t b) { return b ^ ((b >> 3) & 0x70); }

__device__ __forceinline__ void cp16(uint32_t dst, const void* src, int src_bytes) {
    asm volatile("cp.async.cg.shared.global [%0], [%1], 16, %2;"
                 :: "r"(dst), "l"(src), "r"(src_bytes) : "memory");
}
__device__ __forceinline__ void ldsm4(uint32_t* r, uint32_t addr) {
    asm volatile("ldmatrix.sync.aligned.m8n8.x4.shared.b16 {%0,%1,%2,%3}, [%4];"
                 : "=r"(r[0]), "=r"(r[1]), "=r"(r[2]), "=r"(r[3]) : "r"(addr));
}
__device__ __forceinline__ void mma16816(float* d, const uint32_t* a, uint32_t b0, uint32_t b1) {
    asm volatile(
        "mma.sync.aligned.m16n8k16.row.col.f32.bf16.bf16.f32 "
        "{%0,%1,%2,%3}, {%4,%5,%6,%7}, {%8,%9}, {%0,%1,%2,%3};"
        : "+f"(d[0]), "+f"(d[1]), "+f"(d[2]), "+f"(d[3])
        : "r"(a[0]), "r"(a[1]), "r"(a[2]), "r"(a[3]), "r"(b0), "r"(b1));
}

// ---------------------------------------------------------------------------
// Kernel 1: support = softmax(relu(E E^T)) -> bf16 hi/lo split
// ---------------------------------------------------------------------------
__global__ void __launch_bounds__(512) support_kernel(const float* __restrict__ E) {
    const int n   = blockIdx.x;
    const int tid = threadIdx.x;
    __shared__ float en[10];
    __shared__ float redm[16];
    __shared__ float reds[16];

    if (tid < 10) en[tid] = E[n * 10 + tid];
    __syncthreads();

    float lg[10];
    float mx = -1e30f;
#pragma unroll
    for (int it = 0; it < 10; it++) {
        int m = it * 512 + tid;
        float v = -1e30f;
        if (m < N_) {
            const float* em = E + m * 10;
            float s = 0.f;
#pragma unroll
            for (int d = 0; d < 10; d++) s += en[d] * __ldg(em + d);
            v = fmaxf(s, 0.f);
        }
        lg[it] = v;
        mx = fmaxf(mx, v);
    }
#pragma unroll
    for (int o = 16; o > 0; o >>= 1) mx = fmaxf(mx, __shfl_xor_sync(0xffffffffu, mx, o));
    if ((tid & 31) == 0) redm[tid >> 5] = mx;
    __syncthreads();
    if (tid < 32) {
        float v = (tid < 16) ? redm[tid] : -1e30f;
#pragma unroll
        for (int o = 8; o > 0; o >>= 1) v = fmaxf(v, __shfl_xor_sync(0xffffffffu, v, o));
        if (tid == 0) redm[0] = v;
    }
    __syncthreads();
    mx = redm[0];

    float sum = 0.f;
#pragma unroll
    for (int it = 0; it < 10; it++) {
        int m = it * 512 + tid;
        if (m < N_) {
            float e = __expf(lg[it] - mx);
            lg[it] = e;
            sum += e;
        }
    }
#pragma unroll
    for (int o = 16; o > 0; o >>= 1) sum += __shfl_xor_sync(0xffffffffu, sum, o);
    if ((tid & 31) == 0) reds[tid >> 5] = sum;
    __syncthreads();
    if (tid < 32) {
        float v = (tid < 16) ? reds[tid] : 0.f;
#pragma unroll
        for (int o = 8; o > 0; o >>= 1) v += __shfl_xor_sync(0xffffffffu, v, o);
        if (tid == 0) reds[0] = v;
    }
    __syncthreads();
    const float inv = 1.f / reds[0];

#pragma unroll
    for (int it = 0; it < 10; it++) {
        int m = it * 512 + tid;
        if (m < N_) {
            float v = lg[it] * inv;
            __nv_bfloat16 hi = __float2bfloat16_rn(v);
            __nv_bfloat16 lo = __float2bfloat16_rn(v - __bfloat162float(hi));
            g_Sh[(size_t)n * N_ + m] = hi;
            g_Sl[(size_t)n * N_ + m] = lo;
        }
    }
}

// ---------------------------------------------------------------------------
// Kernel 2: x (B,N,C) -> Xb (NCOL, N) bf16 hi/lo: Xb[b*64+c][m] = x[b][m][c]
// ---------------------------------------------------------------------------
__global__ void __launch_bounds__(256) convert_kernel(const float* __restrict__ x) {
    __shared__ float tile[64][65];
    const int m0 = blockIdx.x * 64;
    const int b  = blockIdx.y;
    const int tid = threadIdx.x;

#pragma unroll
    for (int p = 0; p < 16; p++) {
        int idx = p * 256 + tid;
        int mi = idx >> 6, c = idx & 63;
        float v = 0.f;
        if (m0 + mi < N_) v = x[(size_t)b * XROW + (size_t)(m0 + mi) * C_ + c];
        tile[mi][c] = v;
    }
    __syncthreads();
#pragma unroll
    for (int p = 0; p < 16; p++) {
        int idx = p * 256 + tid;
        int c = idx >> 6, mi = idx & 63;
        if (m0 + mi < N_) {
            float v = tile[mi][c];
            __nv_bfloat16 hi = __float2bfloat16_rn(v);
            __nv_bfloat16 lo = __float2bfloat16_rn(v - __bfloat162float(hi));
            size_t o = (size_t)(b * 64 + c) * N_ + m0 + mi;
            g_Bh[o] = hi;
            g_Bl[o] = lo;
        }
    }
}

// ---------------------------------------------------------------------------
// Kernel 3: G = S @ Xb^T via mma.sync bf16, 3-term split, fp32 accumulate.
// CTA tile 128x256x32, 256 threads (8 warps, warp tile 64x64),
// 4-stage cp.async pipeline, SW128-style swizzle on 64B rows, ldmatrix.x4.
// ---------------------------------------------------------------------------
constexpr int SZ_A = TM * 64;          // 8192 B per A matrix (hi or lo)
constexpr int SZ_B = TN * 64;          // 16384 B per B matrix
constexpr int STG  = 2 * SZ_A + 2 * SZ_B;   // 49152 B
constexpr int NSTAGE = 4;
constexpr int GEMM_SMEM = NSTAGE * STG;     // 196608 B

__device__ __forceinline__ void load_stage(uint32_t st, int k0, int bm, int bn, int tid) {
    const uint32_t sAh = st, sAl = st + SZ_A;
    const uint32_t sBh = st + 2 * SZ_A, sBl = st + 2 * SZ_A + SZ_B;
#pragma unroll
    for (int t = 0; t < 2; t++) {
        int q = t * 256 + tid;             // 512 granules of 16B per A matrix
        int row = q >> 2, j = q & 3;
        int gm = bm + row, gk = k0 + j * 8;
        bool v = (gm < N_) && (gk < N_);
        size_t go = v ? ((size_t)gm * N_ + gk) : 0;
        int sz = v ? 16 : 0;
        uint32_t so = swz(row * 64 + j * 16);
        cp16(sAh + so, g_Sh + go, sz);
        cp16(sAl + so, g_Sl + go, sz);
    }
#pragma unroll
    for (int t = 0; t < 4; t++) {
        int q = t * 256 + tid;             // 1024 granules per B matrix
        int row = q >> 2, j = q & 3;
        int gk = k0 + j * 8;
        bool v = gk < N_;
        size_t go = (size_t)(bn + row) * N_ + (v ? gk : 0);
        int sz = v ? 16 : 0;
        uint32_t so = swz(row * 64 + j * 16);
        cp16(sBh + so, g_Bh + go, sz);
        cp16(sBl + so, g_Bl + go, sz);
    }
}

__global__ void __launch_bounds__(256, 1) gemm_mma_kernel() {
    extern __shared__ __align__(1024) char smem[];
    const uint32_t sb = smem_u32(smem);
    const int tid = threadIdx.x, wid = tid >> 5, lid = tid & 31;
    const int bm = blockIdx.y * TM;
    const int bn = blockIdx.x * TN;
    const int wm = wid >> 2;       // 0..1 -> 64 rows each
    const int wn = wid & 3;        // 0..3 -> 64 cols each

    float acc[4][8][4];
#pragma unroll
    for (int mt = 0; mt < 4; mt++)
#pragma unroll
        for (int nt = 0; nt < 8; nt++)
#pragma unroll
            for (int r = 0; r < 4; r++) acc[mt][nt][r] = 0.f;

    // prologue: stages 0..2
#pragma unroll
    for (int s = 0; s < NSTAGE - 1; s++) {
        load_stage(sb + s * STG, s * TK, bm, bn, tid);
        asm volatile("cp.async.commit_group;" ::: "memory");
    }

    // Per-lane ldmatrix address components
    const int aRow = wm * 64 + (lid & 15);                         // + mt*16
    const int aKb  = (lid >> 4) * 16;                              // + ks*32
    const int bRow = wn * 64 + ((lid >> 4) & 1) * 8 + (lid & 7);   // + np*16
    const int bKb  = ((lid >> 3) & 1) * 16;                        // + ks*32

    for (int i = 0; i < KC; i++) {
        asm volatile("cp.async.wait_group 2;" ::: "memory");
        __syncthreads();
        if (i + NSTAGE - 1 < KC)
            load_stage(sb + ((i + NSTAGE - 1) & 3) * STG, (i + NSTAGE - 1) * TK, bm, bn, tid);
        asm volatile("cp.async.commit_group;" ::: "memory");

        const uint32_t st  = sb + (i & 3) * STG;
        const uint32_t sAh = st, sAl = st + SZ_A;
        const uint32_t sBh = st + 2 * SZ_A, sBl = st + 2 * SZ_A + SZ_B;

#pragma unroll
        for (int ks = 0; ks < 2; ks++) {
            uint32_t ah[4][4], al[4][4], bh[4][4], bl[4][4];
#pragma unroll
            for (int mt = 0; mt < 4; mt++) {
                uint32_t off = swz((aRow + mt * 16) * 64 + ks * 32 + aKb);
                ldsm4(ah[mt], sAh + off);
                ldsm4(al[mt], sAl + off);
            }
#pragma unroll
            for (int np = 0; np < 4; np++) {
                uint32_t off = swz((bRow + np * 16) * 64 + ks * 32 + bKb);
                ldsm4(bh[np], sBh + off);
                ldsm4(bl[np], sBl + off);
            }
            // Ah*Bh
#pragma unroll
            for (int mt = 0; mt < 4; mt++)
#pragma unroll
                for (int nt = 0; nt < 8; nt++) {
                    const uint32_t* b = bh[nt >> 1];
                    mma16816(acc[mt][nt], ah[mt], b[(nt & 1) * 2], b[(nt & 1) * 2 + 1]);
                }
            // Al*Bh
#pragma unroll
            for (int mt = 0; mt < 4; mt++)
#pragma unroll
                for (int nt = 0; nt < 8; nt++) {
                    const uint32_t* b = bh[nt >> 1];
                    mma16816(acc[mt][nt], al[mt], b[(nt & 1) * 2], b[(nt & 1) * 2 + 1]);
                }
            // Ah*Bl
#pragma unroll
            for (int mt = 0; mt < 4; mt++)
#pragma unroll
                for (int nt = 0; nt < 8; nt++) {
                    const uint32_t* b = bl[nt >> 1];
                    mma16816(acc[mt][nt], ah[mt], b[(nt & 1) * 2], b[(nt & 1) * 2 + 1]);
                }
        }
    }

    // Store accumulators to g_G (fp32)
    const int rBase = bm + wm * 64 + (lid >> 2);
    const int cBase = bn + wn * 64 + (lid & 3) * 2;
#pragma unroll
    for (int mt = 0; mt < 4; mt++) {
        int r0 = rBase + mt * 16;
        int r1 = r0 + 8;
#pragma unroll
        for (int nt = 0; nt < 8; nt++) {
            int c = cBase + nt * 8;
            if (r0 < N_)
                *(float2*)(g_G + (size_t)r0 * NCOL + c) = make_float2(acc[mt][nt][0], acc[mt][nt][1]);
            if (r1 < N_)
                *(float2*)(g_G + (size_t)r1 * NCOL + c) = make_float2(acc[mt][nt][2], acc[mt][nt][3]);
        }
    }
}

// ---------------------------------------------------------------------------
// Kernel 4: W precompute  g_W[n][e] = sum_d E[n][d] * Wp[d][e],  e in [0,8192)
// Block = (e-tile 2048) x (node-tile 125). Wp e-tile (80 KB) stays L1-resident.
// ---------------------------------------------------------------------------
__global__ void __launch_bounds__(256) wpre_kernel(const float* __restrict__ E,
                                                  const float* __restrict__ Wp) {
    const int e0 = blockIdx.x * 2048;
    const int n0 = blockIdx.y * 125;
    const int tid = threadIdx.x;

    for (int nn = 0; nn < 125; nn++) {
        const int n = n0 + nn;
        float en[10];
#pragma unroll
        for (int d = 0; d < 10; d++) en[d] = __ldg(E + n * 10 + d);
#pragma unroll
        for (int it = 0; it < 2; it++) {
            int ee = e0 + (it * 256 + tid) * 4;
            float4 a = make_float4(0.f, 0.f, 0.f, 0.f);
#pragma unroll
            for (int d = 0; d < 10; d++) {
                float4 w = __ldg((const float4*)(Wp + d * 8192 + ee));
                a.x += en[d] * w.x; a.y += en[d] * w.y;
                a.z += en[d] * w.z; a.w += en[d] * w.w;
            }
            *(float4*)(g_W + (size_t)n * 8192 + ee) = a;
        }
    }
}

// ---------------------------------------------------------------------------
// Kernel 5: epilogue. out[b,n,o] = bias[n,o] + sum_i x[b,n,i]W0[n,i,o] + G[n,b,i]W1[n,i,o]
// W rows streamed from g_W (no per-element d-contraction).
// ---------------------------------------------------------------------------
__global__ void __launch_bounds__(256) epilogue_kernel(
    const float* __restrict__ x,  const float* __restrict__ E,
    const float* __restrict__ bp, float* __restrict__ out)
{
    const int n   = blockIdx.x;
    const int tid = threadIdx.x;
    __shared__ float Ws[8192];     // W0 = Ws[0:4096), W1 = Ws[4096:8192)
    __shared__ float biass[64];
    __shared__ float en[10];

    if (tid < 10) en[tid] = E[n * 10 + tid];

    const float4* wr = (const float4*)(g_W + (size_t)n * 8192);
#pragma unroll
    for (int it = 0; it < 8; it++) {
        int e4 = it * 256 + tid;
        ((float4*)Ws)[e4] = __ldg(wr + e4);
    }
    __syncthreads();
    if (tid < 64) {
        float v = 0.f;
#pragma unroll
        for (int d = 0; d < 10; d++) v += en[d] * bp[d * 64 + tid];
        biass[tid] = v;
    }
    __syncthreads();

    const int o4 = (tid & 15) << 2;
    const int b0 = tid >> 4;
    float acc[4][4];
#pragma unroll
    for (int bi = 0; bi < 4; bi++)
#pragma unroll
        for (int j = 0; j < 4; j++) acc[bi][j] = biass[o4 + j];

    const float* gr = g_G + (size_t)n * NCOL;
    const float* xr = x + (size_t)n * C_;

#pragma unroll 4
    for (int i = 0; i < 64; i++) {
        float4 w0 = *(const float4*)&Ws[i * 64 + o4];
        float4 w1 = *(const float4*)&Ws[4096 + i * 64 + o4];
#pragma unroll
        for (int bi = 0; bi < 4; bi++) {
            int b = b0 + bi * 16;
            float xa = __ldg(xr + (size_t)b * XROW + i);
            float ga = __ldg(gr + b * C_ + i);
            acc[bi][0] += xa * w0.x + ga * w1.x;
            acc[bi][1] += xa * w0.y + ga * w1.y;
            acc[bi][2] += xa * w0.z + ga * w1.z;
            acc[bi][3] += xa * w0.w + ga * w1.w;
        }
    }

#pragma unroll
    for (int bi = 0; bi < 4; bi++) {
        int b = b0 + bi * 16;
        *(float4*)(out + (size_t)b * XROW + (size_t)n * C_ + o4) =
            make_float4(acc[bi][0], acc[bi][1], acc[bi][2], acc[bi][3]);
    }
}

// ---------------------------------------------------------------------------
extern "C" void kernel_launch(void* const* d_in, const int* in_sizes, int n_in,
                              void* d_out, int out_size) {
    (void)in_sizes; (void)n_in; (void)out_size;
    const float* x  = (const float*)d_in[0];   // (64, 5000, 64)
    const float* E  = (const float*)d_in[1];   // (5000, 10)
    const float* Wp = (const float*)d_in[2];   // (10, 2, 64, 64)
    const float* bp = (const float*)d_in[3];   // (10, 64)
    float* out = (float*)d_out;                // (64, 5000, 64)

    static bool attr_done = false;
    if (!attr_done) {
        cudaFuncSetAttribute(gemm_mma_kernel, cudaFuncAttributeMaxDynamicSharedMemorySize, GEMM_SMEM);
        attr_done = true;
    }

    support_kernel<<<N_, 512>>>(E);
    convert_kernel<<<dim3((N_ + 63) / 64, B_), 256>>>(x);
    wpre_kernel   <<<dim3(4, 40), 256>>>(E, Wp);
    gemm_mma_kernel<<<dim3(NCOL / TN, (N_ + TM - 1) / TM), 256, GEMM_SMEM>>>();
    epilogue_kernel<<<N_, 256>>>(x, E, bp, out);
}

// round 5
// speedup vs baseline: 1.0465x; 1.0465x over previous
#include <cuda_runtime.h>
#include <cuda_bf16.h>
#include <cstdint>

// Problem constants
constexpr int B_  = 64;
constexpr int N_  = 5000;
constexpr int C_  = 64;
constexpr int NCOL = B_ * C_;          // 4096
constexpr int XROW = N_ * C_;          // 320000

// GEMM tiling
constexpr int TM = 128;
constexpr int TN = 128;
constexpr int TK = 32;
constexpr int KC = (N_ + TK - 1) / TK;  // 157

// Scratch (device globals; no allocation)
__device__ __align__(1024) __nv_bfloat16 g_Sh[(size_t)N_ * N_];    // 50 MB
__device__ __align__(1024) __nv_bfloat16 g_Sl[(size_t)N_ * N_];    // 50 MB
__device__ __align__(1024) __nv_bfloat16 g_Bh[(size_t)NCOL * N_];  // 41 MB
__device__ __align__(1024) __nv_bfloat16 g_Bl[(size_t)NCOL * N_];  // 41 MB
__device__ __align__(1024) float         g_G [(size_t)N_ * NCOL];  // 82 MB
__device__ __align__(1024) float         g_W [(size_t)N_ * 8192];  // 164 MB

// ---------------------------------------------------------------------------
// Helpers
// ---------------------------------------------------------------------------
__device__ __forceinline__ uint32_t smem_u32(const void* p) {
    uint32_t a;
    asm("{ .reg .u64 t; cvta.to.shared.u64 t, %1; cvt.u32.u64 %0, t; }" : "=r"(a) : "l"(p));
    return a;
}
__device__ __forceinline__ uint32_t swz(uint32_t b) { return b ^ ((b >> 3) & 0x70); }

__device__ __forceinline__ void cp16(uint32_t dst, const void* src, int src_bytes) {
    asm volatile("cp.async.cg.shared.global [%0], [%1], 16, %2;"
                 :: "r"(dst), "l"(src), "r"(src_bytes) : "memory");
}
__device__ __forceinline__ void ldsm4(uint32_t* r, uint32_t addr) {
    asm volatile("ldmatrix.sync.aligned.m8n8.x4.shared.b16 {%0,%1,%2,%3}, [%4];"
                 : "=r"(r[0]), "=r"(r[1]), "=r"(r[2]), "=r"(r[3]) : "r"(addr));
}
__device__ __forceinline__ void mma16816(float* d, const uint32_t* a, uint32_t b0, uint32_t b1) {
    asm volatile(
        "mma.sync.aligned.m16n8k16.row.col.f32.bf16.bf16.f32 "
        "{%0,%1,%2,%3}, {%4,%5,%6,%7}, {%8,%9}, {%0,%1,%2,%3};"
        : "+f"(d[0]), "+f"(d[1]), "+f"(d[2]), "+f"(d[3])
        : "r"(a[0]), "r"(a[1]), "r"(a[2]), "r"(a[3]), "r"(b0), "r"(b1));
}

// ---------------------------------------------------------------------------
// Kernel 1: support = softmax(relu(E E^T)) -> bf16 hi/lo split
// ---------------------------------------------------------------------------
__global__ void __launch_bounds__(512) support_kernel(const float* __restrict__ E) {
    const int n   = blockIdx.x;
    const int tid = threadIdx.x;
    __shared__ float en[10];
    __shared__ float redm[16];
    __shared__ float reds[16];

    if (tid < 10) en[tid] = E[n * 10 + tid];
    __syncthreads();

    float lg[10];
    float mx = -1e30f;
#pragma unroll
    for (int it = 0; it < 10; it++) {
        int m = it * 512 + tid;
        float v = -1e30f;
        if (m < N_) {
            const float* em = E + m * 10;
            float s = 0.f;
#pragma unroll
            for (int d = 0; d < 10; d++) s += en[d] * __ldg(em + d);
            v = fmaxf(s, 0.f);
        }
        lg[it] = v;
        mx = fmaxf(mx, v);
    }
#pragma unroll
    for (int o = 16; o > 0; o >>= 1) mx = fmaxf(mx, __shfl_xor_sync(0xffffffffu, mx, o));
    if ((tid & 31) == 0) redm[tid >> 5] = mx;
    __syncthreads();
    if (tid < 32) {
        float v = (tid < 16) ? redm[tid] : -1e30f;
#pragma unroll
        for (int o = 8; o > 0; o >>= 1) v = fmaxf(v, __shfl_xor_sync(0xffffffffu, v, o));
        if (tid == 0) redm[0] = v;
    }
    __syncthreads();
    mx = redm[0];

    float sum = 0.f;
#pragma unroll
    for (int it = 0; it < 10; it++) {
        int m = it * 512 + tid;
        if (m < N_) {
            float e = __expf(lg[it] - mx);
            lg[it] = e;
            sum += e;
        }
    }
#pragma unroll
    for (int o = 16; o > 0; o >>= 1) sum += __shfl_xor_sync(0xffffffffu, sum, o);
    if ((tid & 31) == 0) reds[tid >> 5] = sum;
    __syncthreads();
    if (tid < 32) {
        float v = (tid < 16) ? reds[tid] : 0.f;
#pragma unroll
        for (int o = 8; o > 0; o >>= 1) v += __shfl_xor_sync(0xffffffffu, v, o);
        if (tid == 0) reds[0] = v;
    }
    __syncthreads();
    const float inv = 1.f / reds[0];

#pragma unroll
    for (int it = 0; it < 10; it++) {
        int m = it * 512 + tid;
        if (m < N_) {
            float v = lg[it] * inv;
            __nv_bfloat16 hi = __float2bfloat16_rn(v);
            __nv_bfloat16 lo = __float2bfloat16_rn(v - __bfloat162float(hi));
            g_Sh[(size_t)n * N_ + m] = hi;
            g_Sl[(size_t)n * N_ + m] = lo;
        }
    }
}

// ---------------------------------------------------------------------------
// Kernel 2: x (B,N,C) -> Xb (NCOL, N) bf16 hi/lo: Xb[b*64+c][m] = x[b][m][c]
// ---------------------------------------------------------------------------
__global__ void __launch_bounds__(256) convert_kernel(const float* __restrict__ x) {
    __shared__ float tile[64][65];
    const int m0 = blockIdx.x * 64;
    const int b  = blockIdx.y;
    const int tid = threadIdx.x;

#pragma unroll
    for (int p = 0; p < 16; p++) {
        int idx = p * 256 + tid;
        int mi = idx >> 6, c = idx & 63;
        float v = 0.f;
        if (m0 + mi < N_) v = x[(size_t)b * XROW + (size_t)(m0 + mi) * C_ + c];
        tile[mi][c] = v;
    }
    __syncthreads();
#pragma unroll
    for (int p = 0; p < 16; p++) {
        int idx = p * 256 + tid;
        int c = idx >> 6, mi = idx & 63;
        if (m0 + mi < N_) {
            float v = tile[mi][c];
            __nv_bfloat16 hi = __float2bfloat16_rn(v);
            __nv_bfloat16 lo = __float2bfloat16_rn(v - __bfloat162float(hi));
            size_t o = (size_t)(b * 64 + c) * N_ + m0 + mi;
            g_Bh[o] = hi;
            g_Bl[o] = lo;
        }
    }
}

// ---------------------------------------------------------------------------
// Kernel 3: G = S @ Xb^T via mma.sync bf16, 3-term split, fp32 accumulate.
// CTA tile 128x128x32, 256 threads (8 warps, warp tile 32x64),
// 3-stage cp.async pipeline (32KB/stage), 2 CTAs/SM, 64B-row swizzle.
// ---------------------------------------------------------------------------
constexpr int SZ_A = TM * 64;          // 8192 B per A matrix (hi or lo)
constexpr int SZ_B = TN * 64;          // 8192 B per B matrix
constexpr int STG  = 2 * SZ_A + 2 * SZ_B;   // 32768 B
constexpr int NSTAGE = 3;
constexpr int GEMM_SMEM = NSTAGE * STG;     // 98304 B

__device__ __forceinline__ void load_stage(uint32_t st, int k0, int bm, int bn, int tid) {
    const uint32_t sAh = st, sAl = st + SZ_A;
    const uint32_t sBh = st + 2 * SZ_A, sBl = st + 2 * SZ_A + SZ_B;
    // A: 128 rows x 32 k (64B/row) = 512 granules of 16B
#pragma unroll
    for (int t = 0; t < 2; t++) {
        int q = t * 256 + tid;
        int row = q >> 2, j = q & 3;
        int gm = bm + row, gk = k0 + j * 8;
        bool v = (gm < N_) && (gk < N_);
        size_t go = v ? ((size_t)gm * N_ + gk) : 0;
        int sz = v ? 16 : 0;
        uint32_t so = swz(row * 64 + j * 16);
        cp16(sAh + so, g_Sh + go, sz);
        cp16(sAl + so, g_Sl + go, sz);
    }
    // B: 128 rows x 32 k
#pragma unroll
    for (int t = 0; t < 2; t++) {
        int q = t * 256 + tid;
        int row = q >> 2, j = q & 3;
        int gk = k0 + j * 8;
        bool v = gk < N_;
        size_t go = (size_t)(bn + row) * N_ + (v ? gk : 0);
        int sz = v ? 16 : 0;
        uint32_t so = swz(row * 64 + j * 16);
        cp16(sBh + so, g_Bh + go, sz);
        cp16(sBl + so, g_Bl + go, sz);
    }
}

__global__ void __launch_bounds__(256, 2) gemm_mma_kernel() {
    extern __shared__ __align__(1024) char smem[];
    const uint32_t sb = smem_u32(smem);
    const int tid = threadIdx.x, wid = tid >> 5, lid = tid & 31;
    const int bm = blockIdx.y * TM;
    const int bn = blockIdx.x * TN;
    const int wm = wid >> 1;       // 0..3 -> 32 rows each
    const int wn = wid & 1;        // 0..1 -> 64 cols each

    float acc[2][8][4];
#pragma unroll
    for (int mt = 0; mt < 2; mt++)
#pragma unroll
        for (int nt = 0; nt < 8; nt++)
#pragma unroll
            for (int r = 0; r < 4; r++) acc[mt][nt][r] = 0.f;

    // prologue: stages 0,1
#pragma unroll
    for (int s = 0; s < NSTAGE - 1; s++) {
        load_stage(sb + s * STG, s * TK, bm, bn, tid);
        asm volatile("cp.async.commit_group;" ::: "memory");
    }

    // Per-lane ldmatrix address components
    const int aRow = wm * 32 + (lid & 15);                         // + mt*16
    const int aKb  = (lid >> 4) * 16;                              // + ks*32
    const int bRow = wn * 64 + ((lid >> 4) & 1) * 8 + (lid & 7);   // + np*16
    const int bKb  = ((lid >> 3) & 1) * 16;                        // + ks*32

    for (int i = 0; i < KC; i++) {
        asm volatile("cp.async.wait_group 1;" ::: "memory");
        __syncthreads();
        if (i + NSTAGE - 1 < KC)
            load_stage(sb + ((i + NSTAGE - 1) % 3) * STG, (i + NSTAGE - 1) * TK, bm, bn, tid);
        asm volatile("cp.async.commit_group;" ::: "memory");

        const uint32_t st  = sb + (i % 3) * STG;
        const uint32_t sAh = st, sAl = st + SZ_A;
        const uint32_t sBh = st + 2 * SZ_A, sBl = st + 2 * SZ_A + SZ_B;

#pragma unroll
        for (int ks = 0; ks < 2; ks++) {
            uint32_t ah[2][4], al[2][4];
#pragma unroll
            for (int mt = 0; mt < 2; mt++) {
                uint32_t off = swz((aRow + mt * 16) * 64 + ks * 32 + aKb);
                ldsm4(ah[mt], sAh + off);
                ldsm4(al[mt], sAl + off);
            }
#pragma unroll
            for (int np = 0; np < 4; np++) {
                uint32_t bh[4], bl[4];
                uint32_t off = swz((bRow + np * 16) * 64 + ks * 32 + bKb);
                ldsm4(bh, sBh + off);
                ldsm4(bl, sBl + off);
#pragma unroll
                for (int half = 0; half < 2; half++) {
                    const int nt = np * 2 + half;
#pragma unroll
                    for (int mt = 0; mt < 2; mt++) {
                        mma16816(acc[mt][nt], ah[mt], bh[half * 2], bh[half * 2 + 1]);
                        mma16816(acc[mt][nt], al[mt], bh[half * 2], bh[half * 2 + 1]);
                        mma16816(acc[mt][nt], ah[mt], bl[half * 2], bl[half * 2 + 1]);
                    }
                }
            }
        }
    }

    // Store accumulators to g_G (fp32)
    const int rBase = bm + wm * 32 + (lid >> 2);
    const int cBase = bn + wn * 64 + (lid & 3) * 2;
#pragma unroll
    for (int mt = 0; mt < 2; mt++) {
        int r0 = rBase + mt * 16;
        int r1 = r0 + 8;
#pragma unroll
        for (int nt = 0; nt < 8; nt++) {
            int c = cBase + nt * 8;
            if (r0 < N_)
                *(float2*)(g_G + (size_t)r0 * NCOL + c) = make_float2(acc[mt][nt][0], acc[mt][nt][1]);
            if (r1 < N_)
                *(float2*)(g_G + (size_t)r1 * NCOL + c) = make_float2(acc[mt][nt][2], acc[mt][nt][3]);
        }
    }
}

// ---------------------------------------------------------------------------
// Kernel 4: W precompute  g_W[n][e] = sum_d E[n][d] * Wp[d][e],  e in [0,8192)
// ---------------------------------------------------------------------------
__global__ void __launch_bounds__(256) wpre_kernel(const float* __restrict__ E,
                                                  const float* __restrict__ Wp) {
    const int e0 = blockIdx.x * 2048;
    const int n0 = blockIdx.y * 125;
    const int tid = threadIdx.x;

    for (int nn = 0; nn < 125; nn++) {
        const int n = n0 + nn;
        float en[10];
#pragma unroll
        for (int d = 0; d < 10; d++) en[d] = __ldg(E + n * 10 + d);
#pragma unroll
        for (int it = 0; it < 2; it++) {
            int ee = e0 + (it * 256 + tid) * 4;
            float4 a = make_float4(0.f, 0.f, 0.f, 0.f);
#pragma unroll
            for (int d = 0; d < 10; d++) {
                float4 w = __ldg((const float4*)(Wp + d * 8192 + ee));
                a.x += en[d] * w.x; a.y += en[d] * w.y;
                a.z += en[d] * w.z; a.w += en[d] * w.w;
            }
            *(float4*)(g_W + (size_t)n * 8192 + ee) = a;
        }
    }
}

// ---------------------------------------------------------------------------
// Kernel 5: epilogue
// ---------------------------------------------------------------------------
__global__ void __launch_bounds__(256) epilogue_kernel(
    const float* __restrict__ x,  const float* __restrict__ E,
    const float* __restrict__ bp, float* __restrict__ out)
{
    const int n   = blockIdx.x;
    const int tid = threadIdx.x;
    __shared__ float Ws[8192];     // W0 = Ws[0:4096), W1 = Ws[4096:8192)
    __shared__ float biass[64];
    __shared__ float en[10];

    if (tid < 10) en[tid] = E[n * 10 + tid];

    const float4* wr = (const float4*)(g_W + (size_t)n * 8192);
#pragma unroll
    for (int it = 0; it < 8; it++) {
        int e4 = it * 256 + tid;
        ((float4*)Ws)[e4] = __ldg(wr + e4);
    }
    __syncthreads();
    if (tid < 64) {
        float v = 0.f;
#pragma unroll
        for (int d = 0; d < 10; d++) v += en[d] * bp[d * 64 + tid];
        biass[tid] = v;
    }
    __syncthreads();

    const int o4 = (tid & 15) << 2;
    const int b0 = tid >> 4;
    float acc[4][4];
#pragma unroll
    for (int bi = 0; bi < 4; bi++)
#pragma unroll
        for (int j = 0; j < 4; j++) acc[bi][j] = biass[o4 + j];

    const float* gr = g_G + (size_t)n * NCOL;
    const float* xr = x + (size_t)n * C_;

#pragma unroll 4
    for (int i = 0; i < 64; i++) {
        float4 w0 = *(const float4*)&Ws[i * 64 + o4];
        float4 w1 = *(const float4*)&Ws[4096 + i * 64 + o4];
#pragma unroll
        for (int bi = 0; bi < 4; bi++) {
            int b = b0 + bi * 16;
            float xa = __ldg(xr + (size_t)b * XROW + i);
            float ga = __ldg(gr + b * C_ + i);
            acc[bi][0] += xa * w0.x + ga * w1.x;
            acc[bi][1] += xa * w0.y + ga * w1.y;
            acc[bi][2] += xa * w0.z + ga * w1.z;
            acc[bi][3] += xa * w0.w + ga * w1.w;
        }
    }

#pragma unroll
    for (int bi = 0; bi < 4; bi++) {
        int b = b0 + bi * 16;
        *(float4*)(out + (size_t)b * XROW + (size_t)n * C_ + o4) =
            make_float4(acc[bi][0], acc[bi][1], acc[bi][2], acc[bi][3]);
    }
}

// ---------------------------------------------------------------------------
extern "C" void kernel_launch(void* const* d_in, const int* in_sizes, int n_in,
                              void* d_out, int out_size) {
    (void)in_sizes; (void)n_in; (void)out_size;
    const float* x  = (const float*)d_in[0];   // (64, 5000, 64)
    const float* E  = (const float*)d_in[1];   // (5000, 10)
    const float* Wp = (const float*)d_in[2];   // (10, 2, 64, 64)
    const float* bp = (const float*)d_in[3];   // (10, 64)
    float* out = (float*)d_out;                // (64, 5000, 64)

    static bool attr_done = false;
    if (!attr_done) {
        cudaFuncSetAttribute(gemm_mma_kernel, cudaFuncAttributeMaxDynamicSharedMemorySize, GEMM_SMEM);
        attr_done = true;
    }

    support_kernel<<<N_, 512>>>(E);
    convert_kernel<<<dim3((N_ + 63) / 64, B_), 256>>>(x);
    wpre_kernel   <<<dim3(4, 40), 256>>>(E, Wp);
    gemm_mma_kernel<<<dim3(NCOL / TN, (N_ + TM - 1) / TM), 256, GEMM_SMEM>>>();
    epilogue_kernel<<<N_, 256>>>(x, E, bp, out);
}

// round 7
// speedup vs baseline: 1.0761x; 1.0283x over previous
#include <cuda_runtime.h>
#include <cuda_bf16.h>
#include <cstdint>

// Problem constants
constexpr int B_  = 64;
constexpr int N_  = 5000;
constexpr int C_  = 64;
constexpr int NCOL = B_ * C_;          // 4096
constexpr int XROW = N_ * C_;          // 320000

// GEMM tiling
constexpr int TM = 128;
constexpr int TN = 128;
constexpr int TK = 32;
constexpr int KC = (N_ + TK - 1) / TK;  // 157 (last chunk k=4992..4999 partial)

// Scratch (device globals; no allocation)
__device__ __align__(1024) __nv_bfloat16 g_Sh[(size_t)N_ * N_];    // 50 MB
__device__ __align__(1024) __nv_bfloat16 g_Sl[(size_t)N_ * N_];    // 50 MB
__device__ __align__(1024) __nv_bfloat16 g_Bh[(size_t)NCOL * N_];  // 41 MB
__device__ __align__(1024) __nv_bfloat16 g_Bl[(size_t)NCOL * N_];  // 41 MB
__device__ __align__(1024) float         g_G [(size_t)N_ * NCOL];  // 82 MB
__device__ __align__(1024) float         g_W [(size_t)N_ * 8192];  // 164 MB

// ---------------------------------------------------------------------------
// Helpers
// ---------------------------------------------------------------------------
__device__ __forceinline__ uint32_t smem_u32(const void* p) {
    uint32_t a;
    asm("{ .reg .u64 t; cvta.to.shared.u64 t, %1; cvt.u32.u64 %0, t; }" : "=r"(a) : "l"(p));
    return a;
}
__device__ __forceinline__ uint32_t swz(uint32_t b) { return b ^ ((b >> 3) & 0x70); }

__device__ __forceinline__ void cp16(uint32_t dst, const void* src, int src_bytes) {
    asm volatile("cp.async.cg.shared.global [%0], [%1], 16, %2;"
                 :: "r"(dst), "l"(src), "r"(src_bytes) : "memory");
}
__device__ __forceinline__ void ldsm4(uint32_t* r, uint32_t addr) {
    asm volatile("ldmatrix.sync.aligned.m8n8.x4.shared.b16 {%0,%1,%2,%3}, [%4];"
                 : "=r"(r[0]), "=r"(r[1]), "=r"(r[2]), "=r"(r[3]) : "r"(addr));
}
__device__ __forceinline__ void mma16816(float* d, const uint32_t* a, uint32_t b0, uint32_t b1) {
    asm volatile(
        "mma.sync.aligned.m16n8k16.row.col.f32.bf16.bf16.f32 "
        "{%0,%1,%2,%3}, {%4,%5,%6,%7}, {%8,%9}, {%0,%1,%2,%3};"
        : "+f"(d[0]), "+f"(d[1]), "+f"(d[2]), "+f"(d[3])
        : "r"(a[0]), "r"(a[1]), "r"(a[2]), "r"(a[3]), "r"(b0), "r"(b1));
}

// ---------------------------------------------------------------------------
// Kernel 1: support = softmax(relu(E E^T)) -> bf16 hi/lo split
// ---------------------------------------------------------------------------
__global__ void __launch_bounds__(512) support_kernel(const float* __restrict__ E) {
    const int n   = blockIdx.x;
    const int tid = threadIdx.x;
    __shared__ float en[10];
    __shared__ float redm[16];
    __shared__ float reds[16];

    if (tid < 10) en[tid] = E[n * 10 + tid];
    __syncthreads();

    float lg[10];
    float mx = -1e30f;
#pragma unroll
    for (int it = 0; it < 10; it++) {
        int m = it * 512 + tid;
        float v = -1e30f;
        if (m < N_) {
            const float* em = E + m * 10;
            float s = 0.f;
#pragma unroll
            for (int d = 0; d < 10; d++) s += en[d] * __ldg(em + d);
            v = fmaxf(s, 0.f);
        }
        lg[it] = v;
        mx = fmaxf(mx, v);
    }
#pragma unroll
    for (int o = 16; o > 0; o >>= 1) mx = fmaxf(mx, __shfl_xor_sync(0xffffffffu, mx, o));
    if ((tid & 31) == 0) redm[tid >> 5] = mx;
    __syncthreads();
    if (tid < 32) {
        float v = (tid < 16) ? redm[tid] : -1e30f;
#pragma unroll
        for (int o = 8; o > 0; o >>= 1) v = fmaxf(v, __shfl_xor_sync(0xffffffffu, v, o));
        if (tid == 0) redm[0] = v;
    }
    __syncthreads();
    mx = redm[0];

    float sum = 0.f;
#pragma unroll
    for (int it = 0; it < 10; it++) {
        int m = it * 512 + tid;
        if (m < N_) {
            float e = __expf(lg[it] - mx);
            lg[it] = e;
            sum += e;
        }
    }
#pragma unroll
    for (int o = 16; o > 0; o >>= 1) sum += __shfl_xor_sync(0xffffffffu, sum, o);
    if ((tid & 31) == 0) reds[tid >> 5] = sum;
    __syncthreads();
    if (tid < 32) {
        float v = (tid < 16) ? reds[tid] : 0.f;
#pragma unroll
        for (int o = 8; o > 0; o >>= 1) v += __shfl_xor_sync(0xffffffffu, v, o);
        if (tid == 0) reds[0] = v;
    }
    __syncthreads();
    const float inv = 1.f / reds[0];

#pragma unroll
    for (int it = 0; it < 10; it++) {
        int m = it * 512 + tid;
        if (m < N_) {
            float v = lg[it] * inv;
            __nv_bfloat16 hi = __float2bfloat16_rn(v);
            __nv_bfloat16 lo = __float2bfloat16_rn(v - __bfloat162float(hi));
            g_Sh[(size_t)n * N_ + m] = hi;
            g_Sl[(size_t)n * N_ + m] = lo;
        }
    }
}

// ---------------------------------------------------------------------------
// Kernel 2: x (B,N,C) -> Xb (NCOL, N) bf16 hi/lo: Xb[b*64+c][m] = x[b][m][c]
// ---------------------------------------------------------------------------
__global__ void __launch_bounds__(256) convert_kernel(const float* __restrict__ x) {
    __shared__ float tile[64][65];
    const int m0 = blockIdx.x * 64;
    const int b  = blockIdx.y;
    const int tid = threadIdx.x;

#pragma unroll
    for (int p = 0; p < 16; p++) {
        int idx = p * 256 + tid;
        int mi = idx >> 6, c = idx & 63;
        float v = 0.f;
        if (m0 + mi < N_) v = x[(size_t)b * XROW + (size_t)(m0 + mi) * C_ + c];
        tile[mi][c] = v;
    }
    __syncthreads();
#pragma unroll
    for (int p = 0; p < 16; p++) {
        int idx = p * 256 + tid;
        int c = idx >> 6, mi = idx & 63;
        if (m0 + mi < N_) {
            float v = tile[mi][c];
            __nv_bfloat16 hi = __float2bfloat16_rn(v);
            __nv_bfloat16 lo = __float2bfloat16_rn(v - __bfloat162float(hi));
            size_t o = (size_t)(b * 64 + c) * N_ + m0 + mi;
            g_Bh[o] = hi;
            g_Bl[o] = lo;
        }
    }
}

// ---------------------------------------------------------------------------
// Kernel 3: G = S @ Xb^T via mma.sync bf16, 3-term split, fp32 accumulate.
// CTA tile 128x128x32, 256 threads (8 warps, warp tile 32x64), 3-stage
// cp.async pipeline, 2 CTAs/SM. Term-major MMA order (RAW gap 4),
// double-buffered B fragments, hoisted load addressing.
// ---------------------------------------------------------------------------
constexpr int SZ_A = TM * 64;          // 8192 B per A matrix (hi or lo)
constexpr int SZ_B = TN * 64;          // 8192 B per B matrix
constexpr int STG  = 2 * SZ_A + 2 * SZ_B;   // 32768 B
constexpr int NSTAGE = 3;
constexpr int GEMM_SMEM = NSTAGE * STG;     // 98304 B

__global__ void __launch_bounds__(256, 2) gemm_mma_kernel() {
    extern __shared__ __align__(1024) char smem[];
    const uint32_t sb = smem_u32(smem);
    const int tid = threadIdx.x, wid = tid >> 5, lid = tid & 31;
    const int bm = blockIdx.y * TM;
    const int bn = blockIdx.x * TN;
    const int wm = wid >> 1;       // 0..3 -> 32 rows each
    const int wn = wid & 1;        // 0..1 -> 64 cols each

    // ---- hoisted per-thread load addressing (2 A granules + 2 B granules) ----
    // granule q in [0,512): row = q>>2 (0..127), j = q&3 (16B along k)
    const int q0 = tid, q1 = 256 + tid;
    const int aR0 = q0 >> 2, aJ0 = q0 & 3;
    const int aR1 = q1 >> 2, aJ1 = q1 & 3;
    const int szA0 = (bm + aR0 < N_) ? 16 : 0;
    const int szA1 = (bm + aR1 < N_) ? 16 : 0;
    const __nv_bfloat16* pAh0 = g_Sh + (size_t)min(bm + aR0, N_ - 1) * N_ + aJ0 * 8;
    const __nv_bfloat16* pAh1 = g_Sh + (size_t)min(bm + aR1, N_ - 1) * N_ + aJ1 * 8;
    const __nv_bfloat16* pAl0 = g_Sl + (pAh0 - g_Sh);
    const __nv_bfloat16* pAl1 = g_Sl + (pAh1 - g_Sh);
    const __nv_bfloat16* pBh0 = g_Bh + (size_t)(bn + aR0) * N_ + aJ0 * 8;
    const __nv_bfloat16* pBh1 = g_Bh + (size_t)(bn + aR1) * N_ + aJ1 * 8;
    const __nv_bfloat16* pBl0 = g_Bl + (pBh0 - g_Bh);
    const __nv_bfloat16* pBl1 = g_Bl + (pBh1 - g_Bh);
    const uint32_t soA0 = swz(aR0 * 64 + aJ0 * 16), soA1 = swz(aR1 * 64 + aJ1 * 16);

    // full-chunk loader (no k predicate)
    auto load_full = [&](uint32_t st, int k0) {
        const size_t kk = (size_t)k0;
        cp16(st + soA0,          pAh0 + kk, szA0);
        cp16(st + SZ_A + soA0,   pAl0 + kk, szA0);
        cp16(st + soA1,          pAh1 + kk, szA1);
        cp16(st + SZ_A + soA1,   pAl1 + kk, szA1);
        const uint32_t bb = st + 2 * SZ_A;
        cp16(bb + soA0,          pBh0 + kk, 16);
        cp16(bb + SZ_B + soA0,   pBl0 + kk, 16);
        cp16(bb + soA1,          pBh1 + kk, 16);
        cp16(bb + SZ_B + soA1,   pBl1 + kk, 16);
    };
    // last chunk: only j==0 granules valid (k 4992..4999)
    auto load_last = [&](uint32_t st, int k0) {
        const size_t kk = (size_t)k0;
        const int vA0 = (aJ0 == 0) ? szA0 : 0, vA1 = (aJ1 == 0) ? szA1 : 0;
        const int vB0 = (aJ0 == 0) ? 16 : 0,  vB1 = (aJ1 == 0) ? 16 : 0;
        cp16(st + soA0,          pAh0 + kk, vA0);
        cp16(st + SZ_A + soA0,   pAl0 + kk, vA0);
        cp16(st + soA1,          pAh1 + kk, vA1);
        cp16(st + SZ_A + soA1,   pAl1 + kk, vA1);
        const uint32_t bb = st + 2 * SZ_A;
        cp16(bb + soA0,          pBh0 + kk, vB0);
        cp16(bb + SZ_B + soA0,   pBl0 + kk, vB0);
        cp16(bb + soA1,          pBh1 + kk, vB1);
        cp16(bb + SZ_B + soA1,   pBl1 + kk, vB1);
    };

    float acc[2][8][4];
#pragma unroll
    for (int mt = 0; mt < 2; mt++)
#pragma unroll
        for (int nt = 0; nt < 8; nt++)
#pragma unroll
            for (int r = 0; r < 4; r++) acc[mt][nt][r] = 0.f;

    // prologue: stages 0,1
    load_full(sb, 0);
    asm volatile("cp.async.commit_group;" ::: "memory");
    load_full(sb + STG, TK);
    asm volatile("cp.async.commit_group;" ::: "memory");

    // Per-lane ldmatrix address components
    const int aRow = wm * 32 + (lid & 15);                         // + mt*16
    const int aKb  = (lid >> 4) * 16;                              // + ks*32
    const int bRow = wn * 64 + ((lid >> 4) & 1) * 8 + (lid & 7);   // + np*16
    const int bKb  = ((lid >> 3) & 1) * 16;                        // + ks*32

    for (int i = 0; i < KC; i++) {
        asm volatile("cp.async.wait_group 1;" ::: "memory");
        __syncthreads();
        {
            const int ip = i + NSTAGE - 1;
            if (ip < KC - 1)       load_full(sb + (ip % 3) * STG, ip * TK);
            else if (ip == KC - 1) load_last(sb + (ip % 3) * STG, ip * TK);
        }
        asm volatile("cp.async.commit_group;" ::: "memory");

        const uint32_t st  = sb + (i % 3) * STG;
        const uint32_t sAh = st, sAl = st + SZ_A;
        const uint32_t sBh = st + 2 * SZ_A, sBl = st + 2 * SZ_A + SZ_B;

#pragma unroll
        for (int ks = 0; ks < 2; ks++) {
            uint32_t ah[2][4], al[2][4];
#pragma unroll
            for (int mt = 0; mt < 2; mt++) {
                uint32_t off = swz((aRow + mt * 16) * 64 + ks * 32 + aKb);
                ldsm4(ah[mt], sAh + off);
                ldsm4(al[mt], sAl + off);
            }
            uint32_t bh[2][4], bl[2][4];
            {
                uint32_t off0 = swz(bRow * 64 + ks * 32 + bKb);
                ldsm4(bh[0], sBh + off0);
                ldsm4(bl[0], sBl + off0);
            }
#pragma unroll
            for (int np = 0; np < 4; np++) {
                const int cur = np & 1;
                if (np < 3) {   // prefetch next B fragment pair
                    uint32_t offn = swz((bRow + (np + 1) * 16) * 64 + ks * 32 + bKb);
                    ldsm4(bh[cur ^ 1], sBh + offn);
                    ldsm4(bl[cur ^ 1], sBl + offn);
                }
                // term-major: hh x4, lh x4, hl x4  (same-acc RAW gap = 4 MMAs)
#pragma unroll
                for (int half = 0; half < 2; half++)
#pragma unroll
                    for (int mt = 0; mt < 2; mt++)
                        mma16816(acc[mt][np * 2 + half], ah[mt],
                                 bh[cur][half * 2], bh[cur][half * 2 + 1]);
#pragma unroll
                for (int half = 0; half < 2; half++)
#pragma unroll
                    for (int mt = 0; mt < 2; mt++)
                        mma16816(acc[mt][np * 2 + half], al[mt],
                                 bh[cur][half * 2], bh[cur][half * 2 + 1]);
#pragma unroll
                for (int half = 0; half < 2; half++)
#pragma unroll
                    for (int mt = 0; mt < 2; mt++)
                        mma16816(acc[mt][np * 2 + half], ah[mt],
                                 bl[cur][half * 2], bl[cur][half * 2 + 1]);
            }
        }
    }

    // Store accumulators to g_G (fp32)
    const int rBase = bm + wm * 32 + (lid >> 2);
    const int cBase = bn + wn * 64 + (lid & 3) * 2;
#pragma unroll
    for (int mt = 0; mt < 2; mt++) {
        int r0 = rBase + mt * 16;
        int r1 = r0 + 8;
#pragma unroll
        for (int nt = 0; nt < 8; nt++) {
            int c = cBase + nt * 8;
            if (r0 < N_)
                *(float2*)(g_G + (size_t)r0 * NCOL + c) = make_float2(acc[mt][nt][0], acc[mt][nt][1]);
            if (r1 < N_)
                *(float2*)(g_G + (size_t)r1 * NCOL + c) = make_float2(acc[mt][nt][2], acc[mt][nt][3]);
        }
    }
}

// ---------------------------------------------------------------------------
// Kernel 4: W precompute  g_W[n][e] = sum_d E[n][d] * Wp[d][e],  e in [0,8192)
// ---------------------------------------------------------------------------
__global__ void __launch_bounds__(256) wpre_kernel(const float* __restrict__ E,
                                                  const float* __restrict__ Wp) {
    const int e0 = blockIdx.x * 2048;
    const int n0 = blockIdx.y * 125;
    const int tid = threadIdx.x;

    for (int nn = 0; nn < 125; nn++) {
        const int n = n0 + nn;
        float en[10];
#pragma unroll
        for (int d = 0; d < 10; d++) en[d] = __ldg(E + n * 10 + d);
#pragma unroll
        for (int it = 0; it < 2; it++) {
            int ee = e0 + (it * 256 + tid) * 4;
            float4 a = make_float4(0.f, 0.f, 0.f, 0.f);
#pragma unroll
            for (int d = 0; d < 10; d++) {
                float4 w = __ldg((const float4*)(Wp + d * 8192 + ee));
                a.x += en[d] * w.x; a.y += en[d] * w.y;
                a.z += en[d] * w.z; a.w += en[d] * w.w;
            }
            *(float4*)(g_W + (size_t)n * 8192 + ee) = a;
        }
    }
}

// ---------------------------------------------------------------------------
// Kernel 5: epilogue
// ---------------------------------------------------------------------------
__global__ void __launch_bounds__(256) epilogue_kernel(
    const float* __restrict__ x,  const float* __restrict__ E,
    const float* __restrict__ bp, float* __restrict__ out)
{
    const int n   = blockIdx.x;
    const int tid = threadIdx.x;
    __shared__ float Ws[8192];     // W0 = Ws[0:4096), W1 = Ws[4096:8192)
    __shared__ float biass[64];
    __shared__ float en[10];

    if (tid < 10) en[tid] = E[n * 10 + tid];

    const float4* wr = (const float4*)(g_W + (size_t)n * 8192);
#pragma unroll
    for (int it = 0; it < 8; it++) {
        int e4 = it * 256 + tid;
        ((float4*)Ws)[e4] = __ldg(wr + e4);
    }
    __syncthreads();
    if (tid < 64) {
        float v = 0.f;
#pragma unroll
        for (int d = 0; d < 10; d++) v += en[d] * bp[d * 64 + tid];
        biass[tid] = v;
    }
    __syncthreads();

    const int o4 = (tid & 15) << 2;
    const int b0 = tid >> 4;
    float acc[4][4];
#pragma unroll
    for (int bi = 0; bi < 4; bi++)
#pragma unroll
        for (int j = 0; j < 4; j++) acc[bi][j] = biass[o4 + j];

    const float* gr = g_G + (size_t)n * NCOL;
    const float* xr = x + (size_t)n * C_;

#pragma unroll 4
    for (int i = 0; i < 64; i++) {
        float4 w0 = *(const float4*)&Ws[i * 64 + o4];
        float4 w1 = *(const float4*)&Ws[4096 + i * 64 + o4];
#pragma unroll
        for (int bi = 0; bi < 4; bi++) {
            int b = b0 + bi * 16;
            float xa = __ldg(xr + (size_t)b * XROW + i);
            float ga = __ldg(gr + b * C_ + i);
            acc[bi][0] += xa * w0.x + ga * w1.x;
            acc[bi][1] += xa * w0.y + ga * w1.y;
            acc[bi][2] += xa * w0.z + ga * w1.z;
            acc[bi][3] += xa * w0.w + ga * w1.w;
        }
    }

#pragma unroll
    for (int bi = 0; bi < 4; bi++) {
        int b = b0 + bi * 16;
        *(float4*)(out + (size_t)b * XROW + (size_t)n * C_ + o4) =
            make_float4(acc[bi][0], acc[bi][1], acc[bi][2], acc[bi][3]);
    }
}

// ---------------------------------------------------------------------------
extern "C" void kernel_launch(void* const* d_in, const int* in_sizes, int n_in,
                              void* d_out, int out_size) {
    (void)in_sizes; (void)n_in; (void)out_size;
    const float* x  = (const float*)d_in[0];   // (64, 5000, 64)
    const float* E  = (const float*)d_in[1];   // (5000, 10)
    const float* Wp = (const float*)d_in[2];   // (10, 2, 64, 64)
    const float* bp = (const float*)d_in[3];   // (10, 64)
    float* out = (float*)d_out;                // (64, 5000, 64)

    static bool attr_done = false;
    if (!attr_done) {
        cudaFuncSetAttribute(gemm_mma_kernel, cudaFuncAttributeMaxDynamicSharedMemorySize, GEMM_SMEM);
        attr_done = true;
    }

    support_kernel<<<N_, 512>>>(E);
    convert_kernel<<<dim3((N_ + 63) / 64, B_), 256>>>(x);
    wpre_kernel   <<<dim3(4, 40), 256>>>(E, Wp);
    gemm_mma_kernel<<<dim3(NCOL / TN, (N_ + TM - 1) / TM), 256, GEMM_SMEM>>>();
    epilogue_kernel<<<N_, 256>>>(x, E, bp, out);
}

// round 8
// speedup vs baseline: 1.4234x; 1.3228x over previous
#include <cuda_runtime.h>
#include <cuda_fp16.h>
#include <cstdint>

// Problem constants
constexpr int B_  = 64;
constexpr int N_  = 5000;
constexpr int C_  = 64;
constexpr int NCOL = B_ * C_;          // 4096
constexpr int XROW = N_ * C_;          // 320000

// GEMM tiling
constexpr int TM = 128;
constexpr int TN = 128;
constexpr int TK = 32;
constexpr int KC = (N_ + TK - 1) / TK;  // 157 (last chunk k=4992..4999 partial)

// Scratch (device globals; no allocation)
__device__ __align__(1024) __half g_Sh[(size_t)N_ * N_];    // 50 MB  (fp16 hi of S)
__device__ __align__(1024) __half g_Sl[(size_t)N_ * N_];    // 50 MB  (fp16 residual of S)
__device__ __align__(1024) __half g_Bx[(size_t)NCOL * N_];  // 41 MB  (fp16 X, K-major)
__device__ __align__(1024) float  g_G [(size_t)N_ * NCOL];  // 82 MB
__device__ __align__(1024) float  g_W [(size_t)N_ * 8192];  // 164 MB

// ---------------------------------------------------------------------------
// Helpers
// ---------------------------------------------------------------------------
__device__ __forceinline__ uint32_t smem_u32(const void* p) {
    uint32_t a;
    asm("{ .reg .u64 t; cvta.to.shared.u64 t, %1; cvt.u32.u64 %0, t; }" : "=r"(a) : "l"(p));
    return a;
}
__device__ __forceinline__ uint32_t swz(uint32_t b) { return b ^ ((b >> 3) & 0x70); }

__device__ __forceinline__ void cp16(uint32_t dst, const void* src, int src_bytes) {
    asm volatile("cp.async.cg.shared.global [%0], [%1], 16, %2;"
                 :: "r"(dst), "l"(src), "r"(src_bytes) : "memory");
}
__device__ __forceinline__ void ldsm4(uint32_t* r, uint32_t addr) {
    asm volatile("ldmatrix.sync.aligned.m8n8.x4.shared.b16 {%0,%1,%2,%3}, [%4];"
                 : "=r"(r[0]), "=r"(r[1]), "=r"(r[2]), "=r"(r[3]) : "r"(addr));
}
__device__ __forceinline__ void mma16816(float* d, const uint32_t* a, uint32_t b0, uint32_t b1) {
    asm volatile(
        "mma.sync.aligned.m16n8k16.row.col.f32.f16.f16.f32 "
        "{%0,%1,%2,%3}, {%4,%5,%6,%7}, {%8,%9}, {%0,%1,%2,%3};"
        : "+f"(d[0]), "+f"(d[1]), "+f"(d[2]), "+f"(d[3])
        : "r"(a[0]), "r"(a[1]), "r"(a[2]), "r"(a[3]), "r"(b0), "r"(b1));
}

// ---------------------------------------------------------------------------
// Kernel 1: support = softmax(relu(E E^T)) -> fp16 hi/lo split
// ---------------------------------------------------------------------------
__global__ void __launch_bounds__(512) support_kernel(const float* __restrict__ E) {
    const int n   = blockIdx.x;
    const int tid = threadIdx.x;
    __shared__ float en[10];
    __shared__ float redm[16];
    __shared__ float reds[16];

    if (tid < 10) en[tid] = E[n * 10 + tid];
    __syncthreads();

    float lg[10];
    float mx = -1e30f;
#pragma unroll
    for (int it = 0; it < 10; it++) {
        int m = it * 512 + tid;
        float v = -1e30f;
        if (m < N_) {
            const float* em = E + m * 10;
            float s = 0.f;
#pragma unroll
            for (int d = 0; d < 10; d++) s += en[d] * __ldg(em + d);
            v = fmaxf(s, 0.f);
        }
        lg[it] = v;
        mx = fmaxf(mx, v);
    }
#pragma unroll
    for (int o = 16; o > 0; o >>= 1) mx = fmaxf(mx, __shfl_xor_sync(0xffffffffu, mx, o));
    if ((tid & 31) == 0) redm[tid >> 5] = mx;
    __syncthreads();
    if (tid < 32) {
        float v = (tid < 16) ? redm[tid] : -1e30f;
#pragma unroll
        for (int o = 8; o > 0; o >>= 1) v = fmaxf(v, __shfl_xor_sync(0xffffffffu, v, o));
        if (tid == 0) redm[0] = v;
    }
    __syncthreads();
    mx = redm[0];

    float sum = 0.f;
#pragma unroll
    for (int it = 0; it < 10; it++) {
        int m = it * 512 + tid;
        if (m < N_) {
            float e = __expf(lg[it] - mx);
            lg[it] = e;
            sum += e;
        }
    }
#pragma unroll
    for (int o = 16; o > 0; o >>= 1) sum += __shfl_xor_sync(0xffffffffu, sum, o);
    if ((tid & 31) == 0) reds[tid >> 5] = sum;
    __syncthreads();
    if (tid < 32) {
        float v = (tid < 16) ? reds[tid] : 0.f;
#pragma unroll
        for (int o = 8; o > 0; o >>= 1) v += __shfl_xor_sync(0xffffffffu, v, o);
        if (tid == 0) reds[0] = v;
    }
    __syncthreads();
    const float inv = 1.f / reds[0];

#pragma unroll
    for (int it = 0; it < 10; it++) {
        int m = it * 512 + tid;
        if (m < N_) {
            float v = lg[it] * inv;
            __half hi = __float2half_rn(v);
            __half lo = __float2half_rn(v - __half2float(hi));
            g_Sh[(size_t)n * N_ + m] = hi;
            g_Sl[(size_t)n * N_ + m] = lo;
        }
    }
}

// ---------------------------------------------------------------------------
// Kernel 2: x (B,N,C) -> Xb (NCOL, N) fp16: Xb[b*64+c][m] = x[b][m][c]
// ---------------------------------------------------------------------------
__global__ void __launch_bounds__(256) convert_kernel(const float* __restrict__ x) {
    __shared__ float tile[64][65];
    const int m0 = blockIdx.x * 64;
    const int b  = blockIdx.y;
    const int tid = threadIdx.x;

#pragma unroll
    for (int p = 0; p < 16; p++) {
        int idx = p * 256 + tid;
        int mi = idx >> 6, c = idx & 63;
        float v = 0.f;
        if (m0 + mi < N_) v = x[(size_t)b * XROW + (size_t)(m0 + mi) * C_ + c];
        tile[mi][c] = v;
    }
    __syncthreads();
#pragma unroll
    for (int p = 0; p < 16; p++) {
        int idx = p * 256 + tid;
        int c = idx >> 6, mi = idx & 63;
        if (m0 + mi < N_) {
            size_t o = (size_t)(b * 64 + c) * N_ + m0 + mi;
            g_Bx[o] = __float2half_rn(tile[mi][c]);
        }
    }
}

// ---------------------------------------------------------------------------
// Kernel 3: G = S @ Xb^T via mma.sync fp16, 2-term split (S_hi + S_lo) * X,
// fp32 accumulate. CTA 128x128x32, 8 warps (32x64 warp tile), 3-stage
// cp.async pipeline, 2 CTAs/SM, term-major MMA order, B-frag double buffer.
// ---------------------------------------------------------------------------
constexpr int SZ_A = TM * 64;          // 8192 B per A matrix (hi or lo)
constexpr int SZ_B = TN * 64;          // 8192 B for the single X matrix
constexpr int STG  = 2 * SZ_A + SZ_B;       // 24576 B
constexpr int NSTAGE = 3;
constexpr int GEMM_SMEM = NSTAGE * STG;     // 73728 B

__global__ void __launch_bounds__(256, 2) gemm_mma_kernel() {
    extern __shared__ __align__(1024) char smem[];
    const uint32_t sb = smem_u32(smem);
    const int tid = threadIdx.x, wid = tid >> 5, lid = tid & 31;
    const int bm = blockIdx.y * TM;
    const int bn = blockIdx.x * TN;
    const int wm = wid >> 1;       // 0..3 -> 32 rows each
    const int wn = wid & 1;        // 0..1 -> 64 cols each

    // ---- hoisted per-thread load addressing ----
    // granule q in [0,512): row = q>>2 (0..127), j = q&3 (16B along k)
    const int q0 = tid, q1 = 256 + tid;
    const int aR0 = q0 >> 2, aJ0 = q0 & 3;
    const int aR1 = q1 >> 2, aJ1 = q1 & 3;
    const int szA0 = (bm + aR0 < N_) ? 16 : 0;
    const int szA1 = (bm + aR1 < N_) ? 16 : 0;
    const __half* pAh0 = g_Sh + (size_t)min(bm + aR0, N_ - 1) * N_ + aJ0 * 8;
    const __half* pAh1 = g_Sh + (size_t)min(bm + aR1, N_ - 1) * N_ + aJ1 * 8;
    const __half* pAl0 = g_Sl + (pAh0 - g_Sh);
    const __half* pAl1 = g_Sl + (pAh1 - g_Sh);
    const __half* pB0  = g_Bx + (size_t)(bn + aR0) * N_ + aJ0 * 8;
    const __half* pB1  = g_Bx + (size_t)(bn + aR1) * N_ + aJ1 * 8;
    const uint32_t soA0 = swz(aR0 * 64 + aJ0 * 16), soA1 = swz(aR1 * 64 + aJ1 * 16);

    auto load_full = [&](uint32_t st, int k0) {
        const size_t kk = (size_t)k0;
        cp16(st + soA0,          pAh0 + kk, szA0);
        cp16(st + SZ_A + soA0,   pAl0 + kk, szA0);
        cp16(st + soA1,          pAh1 + kk, szA1);
        cp16(st + SZ_A + soA1,   pAl1 + kk, szA1);
        const uint32_t bb = st + 2 * SZ_A;
        cp16(bb + soA0,          pB0 + kk, 16);
        cp16(bb + soA1,          pB1 + kk, 16);
    };
    // last chunk: only j==0 granules valid (k 4992..4999)
    auto load_last = [&](uint32_t st, int k0) {
        const size_t kk = (size_t)k0;
        const int vA0 = (aJ0 == 0) ? szA0 : 0, vA1 = (aJ1 == 0) ? szA1 : 0;
        const int vB0 = (aJ0 == 0) ? 16 : 0,  vB1 = (aJ1 == 0) ? 16 : 0;
        cp16(st + soA0,          pAh0 + kk, vA0);
        cp16(st + SZ_A + soA0,   pAl0 + kk, vA0);
        cp16(st + soA1,          pAh1 + kk, vA1);
        cp16(st + SZ_A + soA1,   pAl1 + kk, vA1);
        const uint32_t bb = st + 2 * SZ_A;
        cp16(bb + soA0,          pB0 + kk, vB0);
        cp16(bb + soA1,          pB1 + kk, vB1);
    };

    float acc[2][8][4];
#pragma unroll
    for (int mt = 0; mt < 2; mt++)
#pragma unroll
        for (int nt = 0; nt < 8; nt++)
#pragma unroll
            for (int r = 0; r < 4; r++) acc[mt][nt][r] = 0.f;

    // prologue: stages 0,1
    load_full(sb, 0);
    asm volatile("cp.async.commit_group;" ::: "memory");
    load_full(sb + STG, TK);
    asm volatile("cp.async.commit_group;" ::: "memory");

    // Per-lane ldmatrix address components
    const int aRow = wm * 32 + (lid & 15);                         // + mt*16
    const int aKb  = (lid >> 4) * 16;                              // + ks*32
    const int bRow = wn * 64 + ((lid >> 4) & 1) * 8 + (lid & 7);   // + np*16
    const int bKb  = ((lid >> 3) & 1) * 16;                        // + ks*32

    for (int i = 0; i < KC; i++) {
        asm volatile("cp.async.wait_group 1;" ::: "memory");
        __syncthreads();
        {
            const int ip = i + NSTAGE - 1;
            if (ip < KC - 1)       load_full(sb + (ip % 3) * STG, ip * TK);
            else if (ip == KC - 1) load_last(sb + (ip % 3) * STG, ip * TK);
        }
        asm volatile("cp.async.commit_group;" ::: "memory");

        const uint32_t st  = sb + (i % 3) * STG;
        const uint32_t sAh = st, sAl = st + SZ_A;
        const uint32_t sBx = st + 2 * SZ_A;

#pragma unroll
        for (int ks = 0; ks < 2; ks++) {
            uint32_t ah[2][4], al[2][4];
#pragma unroll
            for (int mt = 0; mt < 2; mt++) {
                uint32_t off = swz((aRow + mt * 16) * 64 + ks * 32 + aKb);
                ldsm4(ah[mt], sAh + off);
                ldsm4(al[mt], sAl + off);
            }
            uint32_t bx[2][4];
            {
                uint32_t off0 = swz(bRow * 64 + ks * 32 + bKb);
                ldsm4(bx[0], sBx + off0);
            }
#pragma unroll
            for (int np = 0; np < 4; np++) {
                const int cur = np & 1;
                if (np < 3) {   // prefetch next B fragment
                    uint32_t offn = swz((bRow + (np + 1) * 16) * 64 + ks * 32 + bKb);
                    ldsm4(bx[cur ^ 1], sBx + offn);
                }
                // term-major: hi x4 then lo x4 (same-acc RAW gap = 4 MMAs)
#pragma unroll
                for (int half = 0; half < 2; half++)
#pragma unroll
                    for (int mt = 0; mt < 2; mt++)
                        mma16816(acc[mt][np * 2 + half], ah[mt],
                                 bx[cur][half * 2], bx[cur][half * 2 + 1]);
#pragma unroll
                for (int half = 0; half < 2; half++)
#pragma unroll
                    for (int mt = 0; mt < 2; mt++)
                        mma16816(acc[mt][np * 2 + half], al[mt],
                                 bx[cur][half * 2], bx[cur][half * 2 + 1]);
            }
        }
    }

    // Store accumulators to g_G (fp32)
    const int rBase = bm + wm * 32 + (lid >> 2);
    const int cBase = bn + wn * 64 + (lid & 3) * 2;
#pragma unroll
    for (int mt = 0; mt < 2; mt++) {
        int r0 = rBase + mt * 16;
        int r1 = r0 + 8;
#pragma unroll
        for (int nt = 0; nt < 8; nt++) {
            int c = cBase + nt * 8;
            if (r0 < N_)
                *(float2*)(g_G + (size_t)r0 * NCOL + c) = make_float2(acc[mt][nt][0], acc[mt][nt][1]);
            if (r1 < N_)
                *(float2*)(g_G + (size_t)r1 * NCOL + c) = make_float2(acc[mt][nt][2], acc[mt][nt][3]);
        }
    }
}

// ---------------------------------------------------------------------------
// Kernel 4: W precompute  g_W[n][e] = sum_d E[n][d] * Wp[d][e],  e in [0,8192)
// ---------------------------------------------------------------------------
__global__ void __launch_bounds__(256) wpre_kernel(const float* __restrict__ E,
                                                  const float* __restrict__ Wp) {
    const int e0 = blockIdx.x * 2048;
    const int n0 = blockIdx.y * 125;
    const int tid = threadIdx.x;

    for (int nn = 0; nn < 125; nn++) {
        const int n = n0 + nn;
        float en[10];
#pragma unroll
        for (int d = 0; d < 10; d++) en[d] = __ldg(E + n * 10 + d);
#pragma unroll
        for (int it = 0; it < 2; it++) {
            int ee = e0 + (it * 256 + tid) * 4;
            float4 a = make_float4(0.f, 0.f, 0.f, 0.f);
#pragma unroll
            for (int d = 0; d < 10; d++) {
                float4 w = __ldg((const float4*)(Wp + d * 8192 + ee));
                a.x += en[d] * w.x; a.y += en[d] * w.y;
                a.z += en[d] * w.z; a.w += en[d] * w.w;
            }
            *(float4*)(g_W + (size_t)n * 8192 + ee) = a;
        }
    }
}

// ---------------------------------------------------------------------------
// Kernel 5: epilogue
// ---------------------------------------------------------------------------
__global__ void __launch_bounds__(256) epilogue_kernel(
    const float* __restrict__ x,  const float* __restrict__ E,
    const float* __restrict__ bp, float* __restrict__ out)
{
    const int n   = blockIdx.x;
    const int tid = threadIdx.x;
    __shared__ float Ws[8192];     // W0 = Ws[0:4096), W1 = Ws[4096:8192)
    __shared__ float biass[64];
    __shared__ float en[10];

    if (tid < 10) en[tid] = E[n * 10 + tid];

    const float4* wr = (const float4*)(g_W + (size_t)n * 8192);
#pragma unroll
    for (int it = 0; it < 8; it++) {
        int e4 = it * 256 + tid;
        ((float4*)Ws)[e4] = __ldg(wr + e4);
    }
    __syncthreads();
    if (tid < 64) {
        float v = 0.f;
#pragma unroll
        for (int d = 0; d < 10; d++) v += en[d] * bp[d * 64 + tid];
        biass[tid] = v;
    }
    __syncthreads();

    const int o4 = (tid & 15) << 2;
    const int b0 = tid >> 4;
    float acc[4][4];
#pragma unroll
    for (int bi = 0; bi < 4; bi++)
#pragma unroll
        for (int j = 0; j < 4; j++) acc[bi][j] = biass[o4 + j];

    const float* gr = g_G + (size_t)n * NCOL;
    const float* xr = x + (size_t)n * C_;

#pragma unroll 4
    for (int i = 0; i < 64; i++) {
        float4 w0 = *(const float4*)&Ws[i * 64 + o4];
        float4 w1 = *(const float4*)&Ws[4096 + i * 64 + o4];
#pragma unroll
        for (int bi = 0; bi < 4; bi++) {
            int b = b0 + bi * 16;
            float xa = __ldg(xr + (size_t)b * XROW + i);
            float ga = __ldg(gr + b * C_ + i);
            acc[bi][0] += xa * w0.x + ga * w1.x;
            acc[bi][1] += xa * w0.y + ga * w1.y;
            acc[bi][2] += xa * w0.z + ga * w1.z;
            acc[bi][3] += xa * w0.w + ga * w1.w;
        }
    }

#pragma unroll
    for (int bi = 0; bi < 4; bi++) {
        int b = b0 + bi * 16;
        *(float4*)(out + (size_t)b * XROW + (size_t)n * C_ + o4) =
            make_float4(acc[bi][0], acc[bi][1], acc[bi][2], acc[bi][3]);
    }
}

// ---------------------------------------------------------------------------
extern "C" void kernel_launch(void* const* d_in, const int* in_sizes, int n_in,
                              void* d_out, int out_size) {
    (void)in_sizes; (void)n_in; (void)out_size;
    const float* x  = (const float*)d_in[0];   // (64, 5000, 64)
    const float* E  = (const float*)d_in[1];   // (5000, 10)
    const float* Wp = (const float*)d_in[2];   // (10, 2, 64, 64)
    const float* bp = (const float*)d_in[3];   // (10, 64)
    float* out = (float*)d_out;                // (64, 5000, 64)

    static bool attr_done = false;
    if (!attr_done) {
        cudaFuncSetAttribute(gemm_mma_kernel, cudaFuncAttributeMaxDynamicSharedMemorySize, GEMM_SMEM);
        attr_done = true;
    }

    support_kernel<<<N_, 512>>>(E);
    convert_kernel<<<dim3((N_ + 63) / 64, B_), 256>>>(x);
    wpre_kernel   <<<dim3(4, 40), 256>>>(E, Wp);
    gemm_mma_kernel<<<dim3(NCOL / TN, (N_ + TM - 1) / TM), 256, GEMM_SMEM>>>();
    epilogue_kernel<<<N_, 256>>>(x, E, bp, out);
}

// round 9
// speedup vs baseline: 2.2711x; 1.5955x over previous
#include <cuda_runtime.h>
#include <cuda_fp16.h>
#include <cstdint>

// Problem constants
constexpr int B_  = 64;
constexpr int N_  = 5000;
constexpr int C_  = 64;
constexpr int NCOL = B_ * C_;          // 4096
constexpr int XROW = N_ * C_;          // 320000

// GEMM tiling
constexpr int TM = 128;
constexpr int TN = 128;
constexpr int TK = 32;
constexpr int KC = (N_ + TK - 1) / TK;  // 157 (last chunk k=4992..4999 partial)

// Scratch (device globals; no allocation)
__device__ __align__(1024) __half g_Sh[(size_t)N_ * N_];    // 50 MB  (fp16 S)
__device__ __align__(1024) __half g_Bx[(size_t)NCOL * N_];  // 41 MB  (fp16 X, K-major)
__device__ __align__(1024) float  g_G [(size_t)N_ * NCOL];  // 82 MB
__device__ __align__(1024) float  g_W [(size_t)N_ * 8192];  // 164 MB

// ---------------------------------------------------------------------------
// Helpers
// ---------------------------------------------------------------------------
__device__ __forceinline__ uint32_t smem_u32(const void* p) {
    uint32_t a;
    asm("{ .reg .u64 t; cvta.to.shared.u64 t, %1; cvt.u32.u64 %0, t; }" : "=r"(a) : "l"(p));
    return a;
}
__device__ __forceinline__ uint32_t swz(uint32_t b) { return b ^ ((b >> 3) & 0x70); }

__device__ __forceinline__ void cp16(uint32_t dst, const void* src, int src_bytes) {
    asm volatile("cp.async.cg.shared.global [%0], [%1], 16, %2;"
                 :: "r"(dst), "l"(src), "r"(src_bytes) : "memory");
}
__device__ __forceinline__ void ldsm4(uint32_t* r, uint32_t addr) {
    asm volatile("ldmatrix.sync.aligned.m8n8.x4.shared.b16 {%0,%1,%2,%3}, [%4];"
                 : "=r"(r[0]), "=r"(r[1]), "=r"(r[2]), "=r"(r[3]) : "r"(addr));
}
__device__ __forceinline__ void mma16816(float* d, const uint32_t* a, uint32_t b0, uint32_t b1) {
    asm volatile(
        "mma.sync.aligned.m16n8k16.row.col.f32.f16.f16.f32 "
        "{%0,%1,%2,%3}, {%4,%5,%6,%7}, {%8,%9}, {%0,%1,%2,%3};"
        : "+f"(d[0]), "+f"(d[1]), "+f"(d[2]), "+f"(d[3])
        : "r"(a[0]), "r"(a[1]), "r"(a[2]), "r"(a[3]), "r"(b0), "r"(b1));
}

// ---------------------------------------------------------------------------
// Kernel 1: support = softmax(relu(E E^T)) -> fp16
// ---------------------------------------------------------------------------
__global__ void __launch_bounds__(512) support_kernel(const float* __restrict__ E) {
    const int n   = blockIdx.x;
    const int tid = threadIdx.x;
    __shared__ float en[10];
    __shared__ float redm[16];
    __shared__ float reds[16];

    if (tid < 10) en[tid] = E[n * 10 + tid];
    __syncthreads();

    float lg[10];
    float mx = -1e30f;
#pragma unroll
    for (int it = 0; it < 10; it++) {
        int m = it * 512 + tid;
        float v = -1e30f;
        if (m < N_) {
            const float* em = E + m * 10;
            float s = 0.f;
#pragma unroll
            for (int d = 0; d < 10; d++) s += en[d] * __ldg(em + d);
            v = fmaxf(s, 0.f);
        }
        lg[it] = v;
        mx = fmaxf(mx, v);
    }
#pragma unroll
    for (int o = 16; o > 0; o >>= 1) mx = fmaxf(mx, __shfl_xor_sync(0xffffffffu, mx, o));
    if ((tid & 31) == 0) redm[tid >> 5] = mx;
    __syncthreads();
    if (tid < 32) {
        float v = (tid < 16) ? redm[tid] : -1e30f;
#pragma unroll
        for (int o = 8; o > 0; o >>= 1) v = fmaxf(v, __shfl_xor_sync(0xffffffffu, v, o));
        if (tid == 0) redm[0] = v;
    }
    __syncthreads();
    mx = redm[0];

    float sum = 0.f;
#pragma unroll
    for (int it = 0; it < 10; it++) {
        int m = it * 512 + tid;
        if (m < N_) {
            float e = __expf(lg[it] - mx);
            lg[it] = e;
            sum += e;
        }
    }
#pragma unroll
    for (int o = 16; o > 0; o >>= 1) sum += __shfl_xor_sync(0xffffffffu, sum, o);
    if ((tid & 31) == 0) reds[tid >> 5] = sum;
    __syncthreads();
    if (tid < 32) {
        float v = (tid < 16) ? reds[tid] : 0.f;
#pragma unroll
        for (int o = 8; o > 0; o >>= 1) v += __shfl_xor_sync(0xffffffffu, v, o);
        if (tid == 0) reds[0] = v;
    }
    __syncthreads();
    const float inv = 1.f / reds[0];

#pragma unroll
    for (int it = 0; it < 10; it++) {
        int m = it * 512 + tid;
        if (m < N_) g_Sh[(size_t)n * N_ + m] = __float2half_rn(lg[it] * inv);
    }
}

// ---------------------------------------------------------------------------
// Kernel 2: x (B,N,C) -> Xb (NCOL, N) fp16: Xb[b*64+c][m] = x[b][m][c]
// ---------------------------------------------------------------------------
__global__ void __launch_bounds__(256) convert_kernel(const float* __restrict__ x) {
    __shared__ float tile[64][65];
    const int m0 = blockIdx.x * 64;
    const int b  = blockIdx.y;
    const int tid = threadIdx.x;

#pragma unroll
    for (int p = 0; p < 16; p++) {
        int idx = p * 256 + tid;
        int mi = idx >> 6, c = idx & 63;
        float v = 0.f;
        if (m0 + mi < N_) v = x[(size_t)b * XROW + (size_t)(m0 + mi) * C_ + c];
        tile[mi][c] = v;
    }
    __syncthreads();
#pragma unroll
    for (int p = 0; p < 16; p++) {
        int idx = p * 256 + tid;
        int c = idx >> 6, mi = idx & 63;
        if (m0 + mi < N_) {
            size_t o = (size_t)(b * 64 + c) * N_ + m0 + mi;
            g_Bx[o] = __float2half_rn(tile[mi][c]);
        }
    }
}

// ---------------------------------------------------------------------------
// Kernel 3: G = S @ Xb^T via mma.sync fp16, single term, fp32 accumulate.
// CTA 128x128x32, 8 warps (32x64 warp tile), 4-stage cp.async pipeline,
// 2 CTAs/SM, B-frag double buffer.
// ---------------------------------------------------------------------------
constexpr int SZ_A = TM * 64;          // 8192 B
constexpr int SZ_B = TN * 64;          // 8192 B
constexpr int STG  = SZ_A + SZ_B;           // 16384 B
constexpr int NSTAGE = 4;
constexpr int GEMM_SMEM = NSTAGE * STG;     // 65536 B

__global__ void __launch_bounds__(256, 2) gemm_mma_kernel() {
    extern __shared__ __align__(1024) char smem[];
    const uint32_t sb = smem_u32(smem);
    const int tid = threadIdx.x, wid = tid >> 5, lid = tid & 31;
    const int bm = blockIdx.y * TM;
    const int bn = blockIdx.x * TN;
    const int wm = wid >> 1;       // 0..3 -> 32 rows each
    const int wn = wid & 1;        // 0..1 -> 64 cols each

    // ---- hoisted per-thread load addressing ----
    // granule q in [0,512): row = q>>2 (0..127), j = q&3 (16B along k)
    const int q0 = tid, q1 = 256 + tid;
    const int aR0 = q0 >> 2, aJ0 = q0 & 3;
    const int aR1 = q1 >> 2, aJ1 = q1 & 3;
    const int szA0 = (bm + aR0 < N_) ? 16 : 0;
    const int szA1 = (bm + aR1 < N_) ? 16 : 0;
    const __half* pA0 = g_Sh + (size_t)min(bm + aR0, N_ - 1) * N_ + aJ0 * 8;
    const __half* pA1 = g_Sh + (size_t)min(bm + aR1, N_ - 1) * N_ + aJ1 * 8;
    const __half* pB0 = g_Bx + (size_t)(bn + aR0) * N_ + aJ0 * 8;
    const __half* pB1 = g_Bx + (size_t)(bn + aR1) * N_ + aJ1 * 8;
    const uint32_t soA0 = swz(aR0 * 64 + aJ0 * 16), soA1 = swz(aR1 * 64 + aJ1 * 16);

    auto load_full = [&](uint32_t st, int k0) {
        const size_t kk = (size_t)k0;
        cp16(st + soA0,          pA0 + kk, szA0);
        cp16(st + soA1,          pA1 + kk, szA1);
        cp16(st + SZ_A + soA0,   pB0 + kk, 16);
        cp16(st + SZ_A + soA1,   pB1 + kk, 16);
    };
    // last chunk: only j==0 granules valid (k 4992..4999)
    auto load_last = [&](uint32_t st, int k0) {
        const size_t kk = (size_t)k0;
        const int vA0 = (aJ0 == 0) ? szA0 : 0, vA1 = (aJ1 == 0) ? szA1 : 0;
        const int vB0 = (aJ0 == 0) ? 16 : 0,  vB1 = (aJ1 == 0) ? 16 : 0;
        cp16(st + soA0,          pA0 + kk, vA0);
        cp16(st + soA1,          pA1 + kk, vA1);
        cp16(st + SZ_A + soA0,   pB0 + kk, vB0);
        cp16(st + SZ_A + soA1,   pB1 + kk, vB1);
    };

    float acc[2][8][4];
#pragma unroll
    for (int mt = 0; mt < 2; mt++)
#pragma unroll
        for (int nt = 0; nt < 8; nt++)
#pragma unroll
            for (int r = 0; r < 4; r++) acc[mt][nt][r] = 0.f;

    // prologue: stages 0..2
#pragma unroll
    for (int s = 0; s < NSTAGE - 1; s++) {
        load_full(sb + s * STG, s * TK);
        asm volatile("cp.async.commit_group;" ::: "memory");
    }

    // Per-lane ldmatrix address components
    const int aRow = wm * 32 + (lid & 15);                         // + mt*16
    const int aKb  = (lid >> 4) * 16;                              // + ks*32
    const int bRow = wn * 64 + ((lid >> 4) & 1) * 8 + (lid & 7);   // + np*16
    const int bKb  = ((lid >> 3) & 1) * 16;                        // + ks*32

    for (int i = 0; i < KC; i++) {
        asm volatile("cp.async.wait_group 2;" ::: "memory");
        __syncthreads();
        {
            const int ip = i + NSTAGE - 1;
            if (ip < KC - 1)       load_full(sb + (ip & 3) * STG, ip * TK);
            else if (ip == KC - 1) load_last(sb + (ip & 3) * STG, ip * TK);
        }
        asm volatile("cp.async.commit_group;" ::: "memory");

        const uint32_t st  = sb + (i & 3) * STG;
        const uint32_t sA = st, sBx = st + SZ_A;

#pragma unroll
        for (int ks = 0; ks < 2; ks++) {
            uint32_t ah[2][4];
#pragma unroll
            for (int mt = 0; mt < 2; mt++) {
                uint32_t off = swz((aRow + mt * 16) * 64 + ks * 32 + aKb);
                ldsm4(ah[mt], sA + off);
            }
            uint32_t bx[2][4];
            {
                uint32_t off0 = swz(bRow * 64 + ks * 32 + bKb);
                ldsm4(bx[0], sBx + off0);
            }
#pragma unroll
            for (int np = 0; np < 4; np++) {
                const int cur = np & 1;
                if (np < 3) {   // prefetch next B fragment
                    uint32_t offn = swz((bRow + (np + 1) * 16) * 64 + ks * 32 + bKb);
                    ldsm4(bx[cur ^ 1], sBx + offn);
                }
#pragma unroll
                for (int half = 0; half < 2; half++)
#pragma unroll
                    for (int mt = 0; mt < 2; mt++)
                        mma16816(acc[mt][np * 2 + half], ah[mt],
                                 bx[cur][half * 2], bx[cur][half * 2 + 1]);
            }
        }
    }

    // Store accumulators to g_G (fp32)
    const int rBase = bm + wm * 32 + (lid >> 2);
    const int cBase = bn + wn * 64 + (lid & 3) * 2;
#pragma unroll
    for (int mt = 0; mt < 2; mt++) {
        int r0 = rBase + mt * 16;
        int r1 = r0 + 8;
#pragma unroll
        for (int nt = 0; nt < 8; nt++) {
            int c = cBase + nt * 8;
            if (r0 < N_)
                *(float2*)(g_G + (size_t)r0 * NCOL + c) = make_float2(acc[mt][nt][0], acc[mt][nt][1]);
            if (r1 < N_)
                *(float2*)(g_G + (size_t)r1 * NCOL + c) = make_float2(acc[mt][nt][2], acc[mt][nt][3]);
        }
    }
}

// ---------------------------------------------------------------------------
// Kernel 4: W precompute  g_W[n][e] = sum_d E[n][d] * Wp[d][e],  e in [0,8192)
// ---------------------------------------------------------------------------
__global__ void __launch_bounds__(256) wpre_kernel(const float* __restrict__ E,
                                                  const float* __restrict__ Wp) {
    const int e0 = blockIdx.x * 2048;
    const int n0 = blockIdx.y * 125;
    const int tid = threadIdx.x;

    for (int nn = 0; nn < 125; nn++) {
        const int n = n0 + nn;
        float en[10];
#pragma unroll
        for (int d = 0; d < 10; d++) en[d] = __ldg(E + n * 10 + d);
#pragma unroll
        for (int it = 0; it < 2; it++) {
            int ee = e0 + (it * 256 + tid) * 4;
            float4 a = make_float4(0.f, 0.f, 0.f, 0.f);
#pragma unroll
            for (int d = 0; d < 10; d++) {
                float4 w = __ldg((const float4*)(Wp + d * 8192 + ee));
                a.x += en[d] * w.x; a.y += en[d] * w.y;
                a.z += en[d] * w.z; a.w += en[d] * w.w;
            }
            *(float4*)(g_W + (size_t)n * 8192 + ee) = a;
        }
    }
}

// ---------------------------------------------------------------------------
// Kernel 5: epilogue
// ---------------------------------------------------------------------------
__global__ void __launch_bounds__(256) epilogue_kernel(
    const float* __restrict__ x,  const float* __restrict__ E,
    const float* __restrict__ bp, float* __restrict__ out)
{
    const int n   = blockIdx.x;
    const int tid = threadIdx.x;
    __shared__ float Ws[8192];     // W0 = Ws[0:4096), W1 = Ws[4096:8192)
    __shared__ float biass[64];
    __shared__ float en[10];

    if (tid < 10) en[tid] = E[n * 10 + tid];

    const float4* wr = (const float4*)(g_W + (size_t)n * 8192);
#pragma unroll
    for (int it = 0; it < 8; it++) {
        int e4 = it * 256 + tid;
        ((float4*)Ws)[e4] = __ldg(wr + e4);
    }
    __syncthreads();
    if (tid < 64) {
        float v = 0.f;
#pragma unroll
        for (int d = 0; d < 10; d++) v += en[d] * bp[d * 64 + tid];
        biass[tid] = v;
    }
    __syncthreads();

    const int o4 = (tid & 15) << 2;
    const int b0 = tid >> 4;
    float acc[4][4];
#pragma unroll
    for (int bi = 0; bi < 4; bi++)
#pragma unroll
        for (int j = 0; j < 4; j++) acc[bi][j] = biass[o4 + j];

    const float* gr = g_G + (size_t)n * NCOL;
    const float* xr = x + (size_t)n * C_;

#pragma unroll 4
    for (int i = 0; i < 64; i++) {
        float4 w0 = *(const float4*)&Ws[i * 64 + o4];
        float4 w1 = *(const float4*)&Ws[4096 + i * 64 + o4];
#pragma unroll
        for (int bi = 0; bi < 4; bi++) {
            int b = b0 + bi * 16;
            float xa = __ldg(xr + (size_t)b * XROW + i);
            float ga = __ldg(gr + b * C_ + i);
            acc[bi][0] += xa * w0.x + ga * w1.x;
            acc[bi][1] += xa * w0.y + ga * w1.y;
            acc[bi][2] += xa * w0.z + ga * w1.z;
            acc[bi][3] += xa * w0.w + ga * w1.w;
        }
    }

#pragma unroll
    for (int bi = 0; bi < 4; bi++) {
        int b = b0 + bi * 16;
        *(float4*)(out + (size_t)b * XROW + (size_t)n * C_ + o4) =
            make_float4(acc[bi][0], acc[bi][1], acc[bi][2], acc[bi][3]);
    }
}

// ---------------------------------------------------------------------------
extern "C" void kernel_launch(void* const* d_in, const int* in_sizes, int n_in,
                              void* d_out, int out_size) {
    (void)in_sizes; (void)n_in; (void)out_size;
    const float* x  = (const float*)d_in[0];   // (64, 5000, 64)
    const float* E  = (const float*)d_in[1];   // (5000, 10)
    const float* Wp = (const float*)d_in[2];   // (10, 2, 64, 64)
    const float* bp = (const float*)d_in[3];   // (10, 64)
    float* out = (float*)d_out;                // (64, 5000, 64)

    static bool attr_done = false;
    if (!attr_done) {
        cudaFuncSetAttribute(gemm_mma_kernel, cudaFuncAttributeMaxDynamicSharedMemorySize, GEMM_SMEM);
        attr_done = true;
    }

    support_kernel<<<N_, 512>>>(E);
    convert_kernel<<<dim3((N_ + 63) / 64, B_), 256>>>(x);
    wpre_kernel   <<<dim3(4, 40), 256>>>(E, Wp);
    gemm_mma_kernel<<<dim3(NCOL / TN, (N_ + TM - 1) / TM), 256, GEMM_SMEM>>>();
    epilogue_kernel<<<N_, 256>>>(x, E, bp, out);
}